// round 2
// baseline (speedup 1.0000x reference)
#include <cuda_runtime.h>
#include <math_constants.h>

// Problem constants
#define BB 2
#define S  2048
#define DD 1024
#define H  16
#define HD 64
#define BH (BB*H)     // 32
#define MROWS (BB*S)  // 4096
#define MASK_N (BB*S*S)  // 8,388,608

// Scratch (device globals: allocation-free)
__device__ float g_q[BH * S * HD];
__device__ float g_k[BH * S * HD];
__device__ float g_v[BH * S * HD];
__device__ unsigned char g_mask_u8[MASK_N];
__device__ int g_mask_mode;  // 0=uint8/bool, 1=int32, 2=float32
__device__ float g_attn_scratch[(size_t)BH * S * S]; // fallback if d_out only holds ctx

// ---------------------------------------------------------------------------
// Mask dtype detection: scan first 2048 words of the raw mask buffer.
// int32 bool -> words in {0,1}; float32 bool -> {0, 0x3f800000};
// uint8 bool -> packed random bytes (neither pattern).
// ---------------------------------------------------------------------------
__global__ void detect_mask_kernel(const unsigned int* __restrict__ w) {
    __shared__ int s_int, s_float;
    if (threadIdx.x == 0) { s_int = 1; s_float = 1; }
    __syncthreads();
    int li = 1, lf = 1;
    for (int i = threadIdx.x; i < 2048; i += 256) {
        unsigned int x = w[i];
        if (x != 0u && x != 1u) li = 0;
        if (x != 0u && x != 0x3f800000u) lf = 0;
    }
    if (!li) atomicAnd(&s_int, 0);
    if (!lf) atomicAnd(&s_float, 0);
    __syncthreads();
    if (threadIdx.x == 0) g_mask_mode = s_int ? 1 : (s_float ? 2 : 0);
}

__global__ void convert_mask_kernel(const void* __restrict__ mraw,
                                    unsigned char* __restrict__ mu8) {
    int i = blockIdx.x * blockDim.x + threadIdx.x;
    if (i >= MASK_N) return;
    int mode = g_mask_mode;
    unsigned char v;
    if (mode == 0)      v = ((const unsigned char*)mraw)[i];
    else if (mode == 1) v = (unsigned char)(((const int*)mraw)[i] != 0);
    else                v = (unsigned char)(((const float*)mraw)[i] != 0.0f);
    mu8[i] = v;
}

// ---------------------------------------------------------------------------
// Projection: C[r, c] = X[r,:] . W[c,:] + bias[c], written into head-split
// layout out[(b*H + h)*S*HD + s*HD + d] with r=(b,s), c=(h,d).
// 128x128 tile, K-step 16, 256 threads, 8x8 per thread (strided 16).
// ---------------------------------------------------------------------------
__global__ void proj_kernel(const float* __restrict__ X, const float* __restrict__ W,
                            const float* __restrict__ bias, float* __restrict__ out) {
    __shared__ float sA[16][129];
    __shared__ float sB[16][129];
    const int tid = threadIdx.x;
    const int tx = tid & 15, ty = tid >> 4;
    const int m0 = blockIdx.y * 128;
    const int n0 = blockIdx.x * 128;

    float acc[8][8];
#pragma unroll
    for (int i = 0; i < 8; i++)
#pragma unroll
        for (int j = 0; j < 8; j++) acc[i][j] = 0.0f;

    for (int k0 = 0; k0 < DD; k0 += 16) {
#pragma unroll
        for (int it = 0; it < 8; it++) {
            int t = tid + it * 256;
            int r = t >> 4, c = t & 15;
            sA[c][r] = X[(size_t)(m0 + r) * DD + k0 + c];
            sB[c][r] = W[(size_t)(n0 + r) * DD + k0 + c];
        }
        __syncthreads();
#pragma unroll
        for (int kk = 0; kk < 16; kk++) {
            float a[8], b[8];
#pragma unroll
            for (int i = 0; i < 8; i++) a[i] = sA[kk][ty + 16 * i];
#pragma unroll
            for (int j = 0; j < 8; j++) b[j] = sB[kk][tx + 16 * j];
#pragma unroll
            for (int i = 0; i < 8; i++)
#pragma unroll
                for (int j = 0; j < 8; j++) acc[i][j] = fmaf(a[i], b[j], acc[i][j]);
        }
        __syncthreads();
    }

#pragma unroll
    for (int i = 0; i < 8; i++) {
        int r = m0 + ty + 16 * i;
        int b = r >> 11;           // r / S
        int s = r & (S - 1);
#pragma unroll
        for (int j = 0; j < 8; j++) {
            int c = n0 + tx + 16 * j;
            int h = c >> 6;        // c / HD
            int d = c & (HD - 1);
            out[(((size_t)(b * H + h)) * S + s) * HD + d] = acc[i][j] + bias[c];
        }
    }
}

// ---------------------------------------------------------------------------
// Scores: attn_raw[bh, q, k] = mask[(bh%B), q, k] ? -inf : (Q.K)/8
// Tile: 32 q x 128 k per block, HD=64 fully in smem. 256 threads,
// per-thread 4q x 4k (k strided 32 for coalesced writes).
// ---------------------------------------------------------------------------
__global__ void scores_kernel(const float* __restrict__ Q, const float* __restrict__ K,
                              const unsigned char* __restrict__ mask,
                              float* __restrict__ attn) {
    __shared__ float sQ[32][64];
    __shared__ float sK[64][137];  // [d][k], pad 137 -> conflict-free ld & st
    const int tid = threadIdx.x;
    const int tx = tid & 31, ty = tid >> 5;
    const int k0 = blockIdx.x * 128;
    const int q0 = blockIdx.y * 32;
    const int bh = blockIdx.z;

    const float* Qb = Q + (size_t)bh * S * HD;
    const float* Kb = K + (size_t)bh * S * HD;

#pragma unroll
    for (int it = 0; it < 8; it++) {     // 32*64 / 256
        int t = tid + it * 256;
        int q = t >> 6, d = t & 63;
        sQ[q][d] = Qb[(size_t)(q0 + q) * HD + d];
    }
#pragma unroll
    for (int it = 0; it < 32; it++) {    // 128*64 / 256
        int t = tid + it * 256;
        int k = t >> 6, d = t & 63;
        sK[d][k] = Kb[(size_t)(k0 + k) * HD + d];
    }
    __syncthreads();

    float acc[4][4];
#pragma unroll
    for (int i = 0; i < 4; i++)
#pragma unroll
        for (int j = 0; j < 4; j++) acc[i][j] = 0.0f;

#pragma unroll 16
    for (int d = 0; d < 64; d++) {
        float a[4], b[4];
#pragma unroll
        for (int i = 0; i < 4; i++) a[i] = sQ[ty + 8 * i][d];
#pragma unroll
        for (int j = 0; j < 4; j++) b[j] = sK[d][tx + 32 * j];
#pragma unroll
        for (int i = 0; i < 4; i++)
#pragma unroll
            for (int j = 0; j < 4; j++) acc[i][j] = fmaf(a[i], b[j], acc[i][j]);
    }

    // torch mask.repeat(H,1,1): head index bh uses mask[bh % B]
    const unsigned char* mb = mask + (size_t)(bh & (BB - 1)) * S * S;
    float* ab = attn + (size_t)bh * S * S;
    const float NEG = -CUDART_INF_F;
#pragma unroll
    for (int i = 0; i < 4; i++) {
        int q = q0 + ty + 8 * i;
#pragma unroll
        for (int j = 0; j < 4; j++) {
            int k = k0 + tx + 32 * j;
            size_t idx = (size_t)q * S + k;
            ab[idx] = mb[idx] ? NEG : acc[i][j] * 0.125f;
        }
    }
}

// ---------------------------------------------------------------------------
// Softmax, in place, one block per row of 2048. 8 values/thread in registers.
// ---------------------------------------------------------------------------
__global__ void softmax_kernel(float* __restrict__ attn) {
    const int tid = threadIdx.x;
    float* p = attn + (size_t)blockIdx.x * S;

    float v[8];
#pragma unroll
    for (int i = 0; i < 8; i++) v[i] = p[tid + 256 * i];

    float m = v[0];
#pragma unroll
    for (int i = 1; i < 8; i++) m = fmaxf(m, v[i]);
#pragma unroll
    for (int o = 16; o > 0; o >>= 1) m = fmaxf(m, __shfl_xor_sync(0xffffffffu, m, o));

    __shared__ float redm[8];
    __shared__ float reds[8];
    if ((tid & 31) == 0) redm[tid >> 5] = m;
    __syncthreads();
    m = redm[0];
#pragma unroll
    for (int i = 1; i < 8; i++) m = fmaxf(m, redm[i]);

    float e[8], s = 0.0f;
#pragma unroll
    for (int i = 0; i < 8; i++) { e[i] = __expf(v[i] - m); s += e[i]; }
#pragma unroll
    for (int o = 16; o > 0; o >>= 1) s += __shfl_xor_sync(0xffffffffu, s, o);
    if ((tid & 31) == 0) reds[tid >> 5] = s;
    __syncthreads();
    s = reds[0];
#pragma unroll
    for (int i = 1; i < 8; i++) s += reds[i];

    float r = 1.0f / s;
#pragma unroll
    for (int i = 0; i < 8; i++) p[tid + 256 * i] = e[i] * r;
}

// ---------------------------------------------------------------------------
// AV: ctx[b, s, h*64+d] = sum_k attn[bh, s, k] * V[bh, k, d]
// Block: 128 q x 64 d, K-step 32. 256 threads: 16q x 2d per thread.
// ---------------------------------------------------------------------------
__global__ void av_kernel(const float* __restrict__ attn, const float* __restrict__ V,
                          float* __restrict__ out) {
    __shared__ float sA[128][33];
    __shared__ float sV[32][64];
    const int tid = threadIdx.x;
    const int tx = tid & 31, ty = tid >> 5;
    const int q0 = blockIdx.x * 128;
    const int bh = blockIdx.y;

    const float* ab = attn + (size_t)bh * S * S;
    const float* Vb = V + (size_t)bh * S * HD;

    float acc[16][2];
#pragma unroll
    for (int i = 0; i < 16; i++) { acc[i][0] = 0.0f; acc[i][1] = 0.0f; }

    for (int k0 = 0; k0 < S; k0 += 32) {
#pragma unroll
        for (int it = 0; it < 16; it++) {  // 128*32 / 256
            int t = tid + it * 256;
            int q = t >> 5, k = t & 31;
            sA[q][k] = ab[(size_t)(q0 + q) * S + k0 + k];
        }
#pragma unroll
        for (int it = 0; it < 8; it++) {   // 32*64 / 256
            int t = tid + it * 256;
            int k = t >> 6, d = t & 63;
            sV[k][d] = Vb[(size_t)(k0 + k) * HD + d];
        }
        __syncthreads();
#pragma unroll 8
        for (int k = 0; k < 32; k++) {
            float b0 = sV[k][tx];
            float b1 = sV[k][tx + 32];
#pragma unroll
            for (int i = 0; i < 16; i++) {
                float a = sA[ty + 8 * i][k];
                acc[i][0] = fmaf(a, b0, acc[i][0]);
                acc[i][1] = fmaf(a, b1, acc[i][1]);
            }
        }
        __syncthreads();
    }

    const int b = bh >> 4, h = bh & 15;
#pragma unroll
    for (int i = 0; i < 16; i++) {
        int s = q0 + ty + 8 * i;
        size_t base = ((size_t)(b * S + s)) * DD + h * HD;
        out[base + tx]      = acc[i][0];
        out[base + tx + 32] = acc[i][1];
    }
}

// ---------------------------------------------------------------------------
extern "C" void kernel_launch(void* const* d_in, const int* in_sizes, int n_in,
                              void* d_out, int out_size) {
    const float* query = (const float*)d_in[0];
    const float* key   = (const float*)d_in[1];
    const float* value = (const float*)d_in[2];
    const void*  mask  = d_in[3];
    const float* Wq = (const float*)d_in[4];
    const float* bq = (const float*)d_in[5];
    const float* Wk = (const float*)d_in[6];
    const float* bk = (const float*)d_in[7];
    const float* Wv = (const float*)d_in[8];
    const float* bv = (const float*)d_in[9];

    float* ctx = (float*)d_out;

    float *qp, *kp, *vp, *attn_fallback;
    unsigned char* mu8;
    cudaGetSymbolAddress((void**)&qp, g_q);
    cudaGetSymbolAddress((void**)&kp, g_k);
    cudaGetSymbolAddress((void**)&vp, g_v);
    cudaGetSymbolAddress((void**)&mu8, g_mask_u8);
    cudaGetSymbolAddress((void**)&attn_fallback, g_attn_scratch);

    const long long CTX_ELEMS  = (long long)BB * S * DD;            // 4,194,304
    const long long ATTN_ELEMS = (long long)BH * S * S;             // 134,217,728
    float* attn = ((long long)out_size >= CTX_ELEMS + ATTN_ELEMS)
                      ? (ctx + CTX_ELEMS) : attn_fallback;

    // Normalize mask to uint8 regardless of marshalled dtype
    detect_mask_kernel<<<1, 256>>>((const unsigned int*)mask);
    convert_mask_kernel<<<MASK_N / 256, 256>>>(mask, mu8);

    dim3 pgrid(DD / 128, MROWS / 128);  // (8, 32)
    proj_kernel<<<pgrid, 256>>>(query, Wq, bq, qp);
    proj_kernel<<<pgrid, 256>>>(key,   Wk, bk, kp);
    proj_kernel<<<pgrid, 256>>>(value, Wv, bv, vp);

    scores_kernel<<<dim3(S / 128, S / 32, BH), 256>>>(qp, kp, mu8, attn);
    softmax_kernel<<<BH * S, 256>>>(attn);
    av_kernel<<<dim3(S / 128, BH), 256>>>(attn, vp, ctx);
}